// round 15
// baseline (speedup 1.0000x reference)
#include <cuda_runtime.h>
#include <cstdint>

// Problem constants (B=2, S=1024, D=1024, E=8, K=2, H=2048)
#define Ntok 2048
#define Ddim 1024
#define Eexp 8
#define Hdim 2048
#define BSD  (2*1024*1024)
#define ZCOEF 1e-4f

// ---------------- scratch (static device globals) ----------------
__device__ float g_zsum;
__device__ float g_psum[Eexp];
__device__ int   g_count[Eexp];
__device__ int   g_list[Eexp * Ntok];
__device__ float g_wlist[Eexp * Ntok];
__device__ float g_act_r[(size_t)Eexp * Ntok * Hdim];   // routed SwiGLU act (wt folded, tf32-rounded)
__device__ float g_act_s[(size_t)Ntok * Hdim];          // shared-expert act (tf32-rounded)
__device__ float g_x_r[(size_t)Ntok * Ddim];            // tf32-rounded x (written by router)

// ---------------- helpers ----------------
__device__ __forceinline__ float rtf(float x) {
    uint32_t r;
    asm("cvt.rna.tf32.f32 %0, %1;" : "=r"(r) : "f"(x));
    return __uint_as_float(r);
}
__device__ __forceinline__ uint32_t rtfb(uint32_t x) {
    uint32_t r;
    asm("cvt.rna.tf32.f32 %0, %1;" : "=r"(r) : "f"(__uint_as_float(x)));
    return r;
}
__device__ __forceinline__ void mma_tf32(float c[4],
    const uint32_t a[4], uint32_t b0, uint32_t b1)
{
    asm volatile(
        "mma.sync.aligned.m16n8k8.row.col.f32.tf32.tf32.f32 "
        "{%0,%1,%2,%3}, {%4,%5,%6,%7}, {%8,%9}, {%0,%1,%2,%3};"
        : "+f"(c[0]), "+f"(c[1]), "+f"(c[2]), "+f"(c[3])
        : "r"(a[0]), "r"(a[1]), "r"(a[2]), "r"(a[3]), "r"(b0), "r"(b1));
}
__device__ __forceinline__ void ldsm4(uint32_t r[4], uint32_t addr) {
    asm volatile("ldmatrix.sync.aligned.m8n8.x4.shared.b16 {%0,%1,%2,%3}, [%4];"
        : "=r"(r[0]), "=r"(r[1]), "=r"(r[2]), "=r"(r[3]) : "r"(addr));
}
__device__ __forceinline__ uint32_t smem_u32(const void* p) {
    uint32_t a;
    asm("{ .reg .u64 t; cvta.to.shared.u64 t, %1; cvt.u32.u64 %0, t; }" : "=r"(a) : "l"(p));
    return a;
}
__device__ __forceinline__ void cpa16(uint32_t dst, const float* src) {
    asm volatile("cp.async.ca.shared.global [%0], [%1], 16;" :: "r"(dst), "l"(src));
}
#define CP_COMMIT() asm volatile("cp.async.commit_group;" ::: "memory")
#define CP_WAIT0()  asm volatile("cp.async.wait_group 0;" ::: "memory")
__device__ __forceinline__ float silu(float x) { return x / (1.f + __expf(-x)); }

// ---------------- init ----------------
__global__ void init_kernel() {
    int t = threadIdx.x;
    if (t == 0) g_zsum = 0.f;
    if (t < Eexp) { g_psum[t] = 0.f; g_count[t] = 0; }
}

// ---------------- router: 8 tokens/block; emits tf32 x; zeroes out ----------------
__global__ __launch_bounds__(256) void router_kernel(
    const float* __restrict__ x,
    const float* __restrict__ rw,
    const float* __restrict__ rb,
    float* __restrict__ xr_out,
    float4* __restrict__ out_zero)
{
    __shared__ float srw[Eexp * Ddim];   // 32 KB
    int tid = threadIdx.x;
    {
        const float4* rw4 = reinterpret_cast<const float4*>(rw);
        float4* srw4 = reinterpret_cast<float4*>(srw);
        #pragma unroll
        for (int i = 0; i < (Eexp * Ddim / 4) / 256; i++)
            srw4[tid + i * 256] = rw4[tid + i * 256];
    }

    // zero the output (256 blocks x 256 threads x 8 float4 == BSD floats)
    {
        int base = blockIdx.x * 256 * 8 + tid;
        #pragma unroll
        for (int i = 0; i < 8; i++)
            out_zero[base + i * 256] = make_float4(0.f, 0.f, 0.f, 0.f);
    }
    __syncthreads();

    int wid = tid >> 5, lane = tid & 31;
    int n = blockIdx.x * 8 + wid;

    const float4* xr = reinterpret_cast<const float4*>(x + (size_t)n * Ddim);
    float4 xv[8];
    #pragma unroll
    for (int i = 0; i < 8; i++) xv[i] = xr[lane + i * 32];

    // write tf32-rounded x
    {
        float4* xo = reinterpret_cast<float4*>(xr_out + (size_t)n * Ddim);
        #pragma unroll
        for (int i = 0; i < 8; i++) {
            float4 t;
            t.x = rtf(xv[i].x); t.y = rtf(xv[i].y); t.z = rtf(xv[i].z); t.w = rtf(xv[i].w);
            xo[lane + i * 32] = t;
        }
    }

    float myLogit = 0.f;
    #pragma unroll
    for (int e = 0; e < Eexp; e++) {
        const float4* we = reinterpret_cast<const float4*>(srw + e * Ddim);
        float s = 0.f;
        #pragma unroll
        for (int i = 0; i < 8; i++) {
            float4 wv = we[lane + i * 32];
            s += xv[i].x * wv.x + xv[i].y * wv.y + xv[i].z * wv.z + xv[i].w * wv.w;
        }
        #pragma unroll
        for (int o = 16; o; o >>= 1) s += __shfl_xor_sync(0xFFFFFFFFu, s, o);
        if (lane == e) myLogit = s;
    }
    float l[Eexp];
    #pragma unroll
    for (int e = 0; e < Eexp; e++) l[e] = __shfl_sync(0xFFFFFFFFu, myLogit, e);

    if (lane == 0) {
        float bsd[Eexp];
        float mx = -1e30f;
        #pragma unroll
        for (int e = 0; e < Eexp; e++) {
            bsd[e] = l[e] + rb[e];
            mx = fmaxf(mx, l[e]);
        }
        int i0 = 0;
        #pragma unroll
        for (int e = 1; e < Eexp; e++) if (bsd[e] > bsd[i0]) i0 = e;
        int i1 = (i0 == 0) ? 1 : 0;
        #pragma unroll
        for (int e = 0; e < Eexp; e++) if (e != i0 && bsd[e] > bsd[i1]) i1 = e;

        float l0 = l[i0], l1 = l[i1];
        float m2 = fmaxf(l0, l1);
        float e0 = expf(l0 - m2), e1 = expf(l1 - m2);
        float inv = 1.f / (e0 + e1);
        float w0 = e0 * inv, w1 = e1 * inv;

        float se = 0.f;
        #pragma unroll
        for (int e = 0; e < Eexp; e++) se += expf(l[e] - mx);
        float z = mx + logf(se);
        atomicAdd(&g_zsum, z * z);
        #pragma unroll
        for (int e = 0; e < Eexp; e++) atomicAdd(&g_psum[e], expf(l[e] - z));

        int p0 = atomicAdd(&g_count[i0], 1);
        g_list[i0 * Ntok + p0]  = n;
        g_wlist[i0 * Ntok + p0] = w0;
        int p1 = atomicAdd(&g_count[i1], 1);
        g_list[i1 * Ntok + p1]  = n;
        g_wlist[i1 * Ntok + p1] = w1;
    }
}

// ---------------- scalar outputs ----------------
__global__ void finalize_kernel(float* __restrict__ out, int out_size) {
    if (out_size >= BSD + 3) {
        float lb = 0.f;
        #pragma unroll
        for (int e = 0; e < Eexp; e++)
            lb += (g_psum[e] / (float)Ntok) * ((float)g_count[e] / (float)Ntok);
        out[BSD + 0] = 0.f;
        out[BSD + 1] = g_zsum / (float)Ntok * ZCOEF;
        out[BSD + 2] = lb * (float)Eexp;
    }
}

// =====================================================================
// ffn1_mma: act[m, n0..n0+127] = rtf(wt * silu(X@Wg^T) * (X@Wu^T))
// 512 threads, ONE CTA/SM, tile 128m x 128n, K-tile 32.
// Stage: A(128x36) + G(128x36) + U(128x36) = 55296 B; 2 stages = 108 KB.
// 16 warps (2m x 8n). B frags rounded post-LDSM. 2-stage, race-free.
// z = 0..7 routed (gathered, wt folded), z = 8 shared (dense).
// =====================================================================
#define STG1F 13824
#define STG1B (STG1F * 4)
__global__ __launch_bounds__(512, 1) void ffn1_mma(
    const float* __restrict__ Xr,
    const float* __restrict__ gw,
    const float* __restrict__ uw,
    const float* __restrict__ shg,
    const float* __restrict__ shu,
    float* __restrict__ actR,
    float* __restrict__ actS)
{
    int e = blockIdx.z;
    bool is_sh = (e == Eexp);
    int M = is_sh ? Ntok : g_count[e];
    int m0 = blockIdx.y * 128;
    if (m0 >= M) return;
    int n0 = blockIdx.x * 128;

    const float* Wg = is_sh ? shg : gw + (size_t)e * Hdim * Ddim;
    const float* Wu = is_sh ? shu : uw + (size_t)e * Hdim * Ddim;
    float* act = is_sh ? actS : actR + (size_t)e * Ntok * Hdim;
    const int* rowidx = is_sh ? nullptr : g_list + e * Ntok;
    const float* wl   = is_sh ? nullptr : g_wlist + e * Ntok;

    extern __shared__ float sm[];
    uint32_t smbase = smem_u32(sm);

    int tid = threadIdx.x, lane = tid & 31, wid = tid >> 5;
    int g = lane >> 2, tig = lane & 3;
    int wm = wid & 1, wn = wid >> 1;        // 2m x 8n
    int mw = wm * 64, nw = wn * 16;

    // loader: 512 threads, each fills 6 x 16B per K-tile (2 A + 2 G + 2 U rows)
    int lr = tid >> 3, lc = tid & 7;        // lr 0..63, lc 0..7
    const float* aptr[2];
    #pragma unroll
    for (int i = 0; i < 2; i++) {
        int mm = m0 + lr + 64 * i;
        int src = mm < M ? mm : (M - 1);
        int row = rowidx ? rowidx[src] : src;
        aptr[i] = Xr + (size_t)row * Ddim + lc * 4;
    }
    const float *gptr[2], *uptr[2];
    #pragma unroll
    for (int i = 0; i < 2; i++) {
        int r = n0 + lr + 64 * i;
        gptr[i] = Wg + (size_t)r * Ddim + lc * 4;
        uptr[i] = Wu + (size_t)r * Ddim + lc * 4;
    }
    uint32_t dA[2], dG[2], dU[2];
    #pragma unroll
    for (int i = 0; i < 2; i++) {
        dA[i] = ((lr + 64 * i) * 36 + lc * 4) * 4;
        dG[i] = (4608 + (lr + 64 * i) * 36 + lc * 4) * 4;
        dU[i] = dG[i] + 4608 * 4;
    }

    uint32_t afoff[4];
    #pragma unroll
    for (int mf = 0; mf < 4; mf++)
        afoff[mf] = ((mw + mf * 16 + (lane & 15)) * 36 + ((lane >> 4) << 2)) * 4;
    uint32_t bgoff, buoff;
    {
        int nrow = nw + ((lane >> 4) << 3) + (lane & 7);
        int cadd = ((lane >> 3) & 1) << 2;
        bgoff = (4608 + nrow * 36 + cadd) * 4;
        buoff = bgoff + 4608 * 4;
    }

    float accg[4][2][4], accu[4][2][4];
    #pragma unroll
    for (int a = 0; a < 4; a++)
        #pragma unroll
        for (int b = 0; b < 2; b++)
            #pragma unroll
            for (int c = 0; c < 4; c++) { accg[a][b][c] = 0.f; accu[a][b][c] = 0.f; }

    {
        uint32_t sb = smbase;
        #pragma unroll
        for (int i = 0; i < 2; i++) {
            cpa16(sb + dA[i], aptr[i]);
            cpa16(sb + dG[i], gptr[i]);
            cpa16(sb + dU[i], uptr[i]);
        }
        CP_COMMIT();
    }

    const int NT = Ddim / 32;
    for (int kt = 0; kt < NT; kt++) {
        int cur = kt & 1;
        CP_WAIT0();          // stage kt ready (only pending group)
        __syncthreads();     // all warps done with stage kt-1 AND see stage kt
        if (kt + 1 < NT) {
            uint32_t sb = smbase + (uint32_t)(cur ^ 1) * STG1B;
            int off = (kt + 1) * 32;
            #pragma unroll
            for (int i = 0; i < 2; i++) {
                cpa16(sb + dA[i], aptr[i] + off);
                cpa16(sb + dG[i], gptr[i] + off);
                cpa16(sb + dU[i], uptr[i] + off);
            }
            CP_COMMIT();
        }
        uint32_t stb = smbase + (uint32_t)cur * STG1B;
        #pragma unroll
        for (int s = 0; s < 4; s++) {
            uint32_t koff = s * 32;
            uint32_t af[4][4], bg[4], bu[4];
            ldsm4(af[0], stb + afoff[0] + koff);
            ldsm4(af[1], stb + afoff[1] + koff);
            ldsm4(af[2], stb + afoff[2] + koff);
            ldsm4(af[3], stb + afoff[3] + koff);
            ldsm4(bg, stb + bgoff + koff);
            ldsm4(bu, stb + buoff + koff);
            #pragma unroll
            for (int j = 0; j < 4; j++) { bg[j] = rtfb(bg[j]); bu[j] = rtfb(bu[j]); }
            #pragma unroll
            for (int mf = 0; mf < 4; mf++) {
                mma_tf32(accg[mf][0], af[mf], bg[0], bg[1]);
                mma_tf32(accg[mf][1], af[mf], bg[2], bg[3]);
                mma_tf32(accu[mf][0], af[mf], bu[0], bu[1]);
                mma_tf32(accu[mf][1], af[mf], bu[2], bu[3]);
            }
        }
    }

    #pragma unroll
    for (int mf = 0; mf < 4; mf++) {
        int m1 = m0 + mw + mf * 16 + g;
        int m2 = m1 + 8;
        float wt1 = (m1 < M) ? (wl ? wl[m1] : 1.f) : 0.f;
        float wt2 = (m2 < M) ? (wl ? wl[m2] : 1.f) : 0.f;
        #pragma unroll
        for (int nf = 0; nf < 2; nf++) {
            int n = n0 + nw + nf * 8 + 2 * tig;
            if (m1 < M) {
                float2 o;
                o.x = rtf(wt1 * silu(accg[mf][nf][0]) * accu[mf][nf][0]);
                o.y = rtf(wt1 * silu(accg[mf][nf][1]) * accu[mf][nf][1]);
                *reinterpret_cast<float2*>(act + (size_t)m1 * Hdim + n) = o;
            }
            if (m2 < M) {
                float2 o;
                o.x = rtf(wt2 * silu(accg[mf][nf][2]) * accu[mf][nf][2]);
                o.y = rtf(wt2 * silu(accg[mf][nf][3]) * accu[mf][nf][3]);
                *reinterpret_cast<float2*>(act + (size_t)m2 * Hdim + n) = o;
            }
        }
    }
}

// =====================================================================
// ffn2_mma: out += ACT @ Wd^T  (all atomic; out pre-zeroed by router)
// z = 0..7 routed, z = 8 shared. All fills .ca. 2-stage, race-free.
// 256 threads, 2 CTAs/SM, tile 128x128 (unchanged from best config).
// =====================================================================
#define STG2F 9216
#define STG2B (STG2F * 4)
__global__ __launch_bounds__(256, 2) void ffn2_mma(
    const float* __restrict__ actRb,
    const float* __restrict__ actSb,
    const float* __restrict__ dw,
    const float* __restrict__ shd,
    float* __restrict__ OUT)
{
    int e = blockIdx.z;
    bool is_sh = (e == Eexp);
    int M = is_sh ? Ntok : g_count[e];
    int m0 = blockIdx.y * 128;
    if (m0 >= M) return;
    int n0 = blockIdx.x * 128;

    const float* Wd  = is_sh ? shd : dw + (size_t)e * Ddim * Hdim;
    const float* act = is_sh ? actSb : actRb + (size_t)e * Ntok * Hdim;
    const int* rowidx = is_sh ? nullptr : g_list + e * Ntok;

    extern __shared__ float sm[];
    uint32_t smbase = smem_u32(sm);

    int tid = threadIdx.x, lane = tid & 31, wid = tid >> 5;
    int g = lane >> 2, tig = lane & 3;
    int wm = wid >> 2, wn = wid & 3;
    int mw = wm * 64, nw = wn * 32;

    int lr = tid >> 3, lc = tid & 7;
    const float* aptr[4];
    const float* bptr[4];
    #pragma unroll
    for (int i = 0; i < 4; i++) {
        int mm = m0 + lr + 32 * i;
        int src = mm < M ? mm : (M - 1);
        aptr[i] = act + (size_t)src * Hdim + lc * 4;
        bptr[i] = Wd  + (size_t)(n0 + lr + 32 * i) * Hdim + lc * 4;
    }
    uint32_t dA[4], dB[4];
    #pragma unroll
    for (int i = 0; i < 4; i++) {
        dA[i] = ((lr + 32 * i) * 36 + lc * 4) * 4;
        dB[i] = (4608 + (lr + 32 * i) * 36 + lc * 4) * 4;
    }

    uint32_t afoff[4];
    #pragma unroll
    for (int mf = 0; mf < 4; mf++)
        afoff[mf] = ((mw + mf * 16 + (lane & 15)) * 36 + ((lane >> 4) << 2)) * 4;
    uint32_t bfoff[2];
    {
        int nrow = nw + ((lane >> 4) << 3) + (lane & 7);
        int cadd = ((lane >> 3) & 1) << 2;
        #pragma unroll
        for (int p = 0; p < 2; p++)
            bfoff[p] = (4608 + (nrow + p * 16) * 36 + cadd) * 4;
    }

    float acc[4][4][4];
    #pragma unroll
    for (int a = 0; a < 4; a++)
        #pragma unroll
        for (int b = 0; b < 4; b++)
            #pragma unroll
            for (int c = 0; c < 4; c++) acc[a][b][c] = 0.f;

    {
        uint32_t sb = smbase;
        #pragma unroll
        for (int i = 0; i < 4; i++) { cpa16(sb + dA[i], aptr[i]); cpa16(sb + dB[i], bptr[i]); }
        CP_COMMIT();
    }

    const int NT = Hdim / 32;
    for (int kt = 0; kt < NT; kt++) {
        int cur = kt & 1;
        CP_WAIT0();
        __syncthreads();
        if (kt + 1 < NT) {
            uint32_t sb = smbase + (uint32_t)(cur ^ 1) * STG2B;
            int off = (kt + 1) * 32;
            #pragma unroll
            for (int i = 0; i < 4; i++) { cpa16(sb + dA[i], aptr[i] + off); cpa16(sb + dB[i], bptr[i] + off); }
            CP_COMMIT();
        }
        uint32_t stb = smbase + (uint32_t)cur * STG2B;
        #pragma unroll
        for (int s = 0; s < 4; s++) {
            uint32_t koff = s * 32;
            uint32_t af[4][4], bf[2][4];
            ldsm4(af[0], stb + afoff[0] + koff);
            ldsm4(af[1], stb + afoff[1] + koff);
            ldsm4(af[2], stb + afoff[2] + koff);
            ldsm4(af[3], stb + afoff[3] + koff);
            ldsm4(bf[0], stb + bfoff[0] + koff);
            ldsm4(bf[1], stb + bfoff[1] + koff);
            #pragma unroll
            for (int p = 0; p < 2; p++)
                #pragma unroll
                for (int j = 0; j < 4; j++) bf[p][j] = rtfb(bf[p][j]);
            #pragma unroll
            for (int mf = 0; mf < 4; mf++)
                #pragma unroll
                for (int p = 0; p < 2; p++) {
                    mma_tf32(acc[mf][2*p  ], af[mf], bf[p][0], bf[p][1]);
                    mma_tf32(acc[mf][2*p+1], af[mf], bf[p][2], bf[p][3]);
                }
        }
    }

    #pragma unroll
    for (int mf = 0; mf < 4; mf++) {
        int m1 = m0 + mw + mf * 16 + g;
        int m2 = m1 + 8;
        #pragma unroll
        for (int nf = 0; nf < 4; nf++) {
            int n = n0 + nw + nf * 8 + 2 * tig;
            if (m1 < M) {
                int tok = rowidx ? rowidx[m1] : m1;
                float* p = OUT + (size_t)tok * Ddim + n;
                atomicAdd(p,     acc[mf][nf][0]);
                atomicAdd(p + 1, acc[mf][nf][1]);
            }
            if (m2 < M) {
                int tok = rowidx ? rowidx[m2] : m2;
                float* p = OUT + (size_t)tok * Ddim + n;
                atomicAdd(p,     acc[mf][nf][2]);
                atomicAdd(p + 1, acc[mf][nf][3]);
            }
        }
    }
}

// ---------------- launch ----------------
#define FFN1_SMEM (2 * STG1B)    // 110592 B
#define FFN2_SMEM (2 * STG2B)    // 73728 B

extern "C" void kernel_launch(void* const* d_in, const int* in_sizes, int n_in,
                              void* d_out, int out_size)
{
    const float* x   = (const float*)d_in[0];
    const float* rw  = (const float*)d_in[1];
    const float* rb  = (const float*)d_in[2];
    const float* gw  = (const float*)d_in[3];
    const float* uw  = (const float*)d_in[4];
    const float* dw  = (const float*)d_in[5];
    const float* shg = (const float*)d_in[6];
    const float* shu = (const float*)d_in[7];
    const float* shd = (const float*)d_in[8];
    float* out = (float*)d_out;

    float *act_r, *act_s, *x_r;
    cudaGetSymbolAddress((void**)&act_r, g_act_r);
    cudaGetSymbolAddress((void**)&act_s, g_act_s);
    cudaGetSymbolAddress((void**)&x_r,   g_x_r);

    cudaFuncSetAttribute(ffn1_mma, cudaFuncAttributeMaxDynamicSharedMemorySize, FFN1_SMEM);
    cudaFuncSetAttribute(ffn2_mma, cudaFuncAttributeMaxDynamicSharedMemorySize, FFN2_SMEM);

    init_kernel<<<1, 32>>>();
    // router: logits/top-2/lists + tf32 x + zeroes out
    router_kernel<<<Ntok / 8, 256>>>(x, rw, rb, x_r, (float4*)out);
    finalize_kernel<<<1, 1>>>(out, out_size);

    // gate/up + SwiGLU: 512-thread CTAs, 128x128 tiles; z 0..7 routed, z 8 shared
    ffn1_mma<<<dim3(Hdim/128, Ntok/128, Eexp + 1), 512, FFN1_SMEM>>>(
        x_r, gw, uw, shg, shu, act_r, act_s);

    // down-proj: single all-atomic launch over pre-zeroed out
    ffn2_mma<<<dim3(Ddim/128, Ntok/128, Eexp + 1), 256, FFN2_SMEM>>>(
        act_r, act_s, dw, shd, out);
}

// round 16
// speedup vs baseline: 1.0512x; 1.0512x over previous
#include <cuda_runtime.h>
#include <cstdint>

// Problem constants (B=2, S=1024, D=1024, E=8, K=2, H=2048)
#define Ntok 2048
#define Ddim 1024
#define Eexp 8
#define Hdim 2048
#define BSD  (2*1024*1024)
#define ZCOEF 1e-4f

// ---------------- scratch (static device globals) ----------------
__device__ float g_zsum;
__device__ float g_psum[Eexp];
__device__ int   g_count[Eexp];
__device__ int   g_list[Eexp * Ntok];
__device__ float g_wlist[Eexp * Ntok];
__device__ float g_act_r[(size_t)Eexp * Ntok * Hdim];   // routed SwiGLU act (wt folded, tf32-rounded)
__device__ float g_act_s[(size_t)Ntok * Hdim];          // shared-expert act (tf32-rounded)
__device__ float g_x_r[(size_t)Ntok * Ddim];            // tf32-rounded x (written by router)

// ---------------- helpers ----------------
__device__ __forceinline__ float rtf(float x) {
    uint32_t r;
    asm("cvt.rna.tf32.f32 %0, %1;" : "=r"(r) : "f"(x));
    return __uint_as_float(r);
}
__device__ __forceinline__ uint32_t rtfb(uint32_t x) {
    uint32_t r;
    asm("cvt.rna.tf32.f32 %0, %1;" : "=r"(r) : "f"(__uint_as_float(x)));
    return r;
}
__device__ __forceinline__ void mma_tf32(float c[4],
    const uint32_t a[4], uint32_t b0, uint32_t b1)
{
    asm volatile(
        "mma.sync.aligned.m16n8k8.row.col.f32.tf32.tf32.f32 "
        "{%0,%1,%2,%3}, {%4,%5,%6,%7}, {%8,%9}, {%0,%1,%2,%3};"
        : "+f"(c[0]), "+f"(c[1]), "+f"(c[2]), "+f"(c[3])
        : "r"(a[0]), "r"(a[1]), "r"(a[2]), "r"(a[3]), "r"(b0), "r"(b1));
}
__device__ __forceinline__ void ldsm4(uint32_t r[4], uint32_t addr) {
    asm volatile("ldmatrix.sync.aligned.m8n8.x4.shared.b16 {%0,%1,%2,%3}, [%4];"
        : "=r"(r[0]), "=r"(r[1]), "=r"(r[2]), "=r"(r[3]) : "r"(addr));
}
__device__ __forceinline__ uint32_t smem_u32(const void* p) {
    uint32_t a;
    asm("{ .reg .u64 t; cvta.to.shared.u64 t, %1; cvt.u32.u64 %0, t; }" : "=r"(a) : "l"(p));
    return a;
}
__device__ __forceinline__ void cpa16(uint32_t dst, const float* src) {
    asm volatile("cp.async.ca.shared.global [%0], [%1], 16;" :: "r"(dst), "l"(src));
}
#define CP_COMMIT() asm volatile("cp.async.commit_group;" ::: "memory")
#define CP_WAIT0()  asm volatile("cp.async.wait_group 0;" ::: "memory")
__device__ __forceinline__ float silu(float x) { return x / (1.f + __expf(-x)); }

// ---------------- init ----------------
__global__ void init_kernel() {
    int t = threadIdx.x;
    if (t == 0) g_zsum = 0.f;
    if (t < Eexp) { g_psum[t] = 0.f; g_count[t] = 0; }
}

// ---------------- router: 8 tokens/block; emits tf32 x; zeroes out ----------------
__global__ __launch_bounds__(256) void router_kernel(
    const float* __restrict__ x,
    const float* __restrict__ rw,
    const float* __restrict__ rb,
    float* __restrict__ xr_out,
    float4* __restrict__ out_zero)
{
    __shared__ float srw[Eexp * Ddim];   // 32 KB
    int tid = threadIdx.x;
    {
        const float4* rw4 = reinterpret_cast<const float4*>(rw);
        float4* srw4 = reinterpret_cast<float4*>(srw);
        #pragma unroll
        for (int i = 0; i < (Eexp * Ddim / 4) / 256; i++)
            srw4[tid + i * 256] = rw4[tid + i * 256];
    }

    // zero the output (256 blocks x 256 threads x 8 float4 == BSD floats)
    {
        int base = blockIdx.x * 256 * 8 + tid;
        #pragma unroll
        for (int i = 0; i < 8; i++)
            out_zero[base + i * 256] = make_float4(0.f, 0.f, 0.f, 0.f);
    }
    __syncthreads();

    int wid = tid >> 5, lane = tid & 31;
    int n = blockIdx.x * 8 + wid;

    const float4* xr = reinterpret_cast<const float4*>(x + (size_t)n * Ddim);
    float4 xv[8];
    #pragma unroll
    for (int i = 0; i < 8; i++) xv[i] = xr[lane + i * 32];

    // write tf32-rounded x
    {
        float4* xo = reinterpret_cast<float4*>(xr_out + (size_t)n * Ddim);
        #pragma unroll
        for (int i = 0; i < 8; i++) {
            float4 t;
            t.x = rtf(xv[i].x); t.y = rtf(xv[i].y); t.z = rtf(xv[i].z); t.w = rtf(xv[i].w);
            xo[lane + i * 32] = t;
        }
    }

    float myLogit = 0.f;
    #pragma unroll
    for (int e = 0; e < Eexp; e++) {
        const float4* we = reinterpret_cast<const float4*>(srw + e * Ddim);
        float s = 0.f;
        #pragma unroll
        for (int i = 0; i < 8; i++) {
            float4 wv = we[lane + i * 32];
            s += xv[i].x * wv.x + xv[i].y * wv.y + xv[i].z * wv.z + xv[i].w * wv.w;
        }
        #pragma unroll
        for (int o = 16; o; o >>= 1) s += __shfl_xor_sync(0xFFFFFFFFu, s, o);
        if (lane == e) myLogit = s;
    }
    float l[Eexp];
    #pragma unroll
    for (int e = 0; e < Eexp; e++) l[e] = __shfl_sync(0xFFFFFFFFu, myLogit, e);

    if (lane == 0) {
        float bsd[Eexp];
        float mx = -1e30f;
        #pragma unroll
        for (int e = 0; e < Eexp; e++) {
            bsd[e] = l[e] + rb[e];
            mx = fmaxf(mx, l[e]);
        }
        int i0 = 0;
        #pragma unroll
        for (int e = 1; e < Eexp; e++) if (bsd[e] > bsd[i0]) i0 = e;
        int i1 = (i0 == 0) ? 1 : 0;
        #pragma unroll
        for (int e = 0; e < Eexp; e++) if (e != i0 && bsd[e] > bsd[i1]) i1 = e;

        float l0 = l[i0], l1 = l[i1];
        float m2 = fmaxf(l0, l1);
        float e0 = expf(l0 - m2), e1 = expf(l1 - m2);
        float inv = 1.f / (e0 + e1);
        float w0 = e0 * inv, w1 = e1 * inv;

        float se = 0.f;
        #pragma unroll
        for (int e = 0; e < Eexp; e++) se += expf(l[e] - mx);
        float z = mx + logf(se);
        atomicAdd(&g_zsum, z * z);
        #pragma unroll
        for (int e = 0; e < Eexp; e++) atomicAdd(&g_psum[e], expf(l[e] - z));

        int p0 = atomicAdd(&g_count[i0], 1);
        g_list[i0 * Ntok + p0]  = n;
        g_wlist[i0 * Ntok + p0] = w0;
        int p1 = atomicAdd(&g_count[i1], 1);
        g_list[i1 * Ntok + p1]  = n;
        g_wlist[i1 * Ntok + p1] = w1;
    }
}

// ---------------- scalar outputs ----------------
__global__ void finalize_kernel(float* __restrict__ out, int out_size) {
    if (out_size >= BSD + 3) {
        float lb = 0.f;
        #pragma unroll
        for (int e = 0; e < Eexp; e++)
            lb += (g_psum[e] / (float)Ntok) * ((float)g_count[e] / (float)Ntok);
        out[BSD + 0] = 0.f;
        out[BSD + 1] = g_zsum / (float)Ntok * ZCOEF;
        out[BSD + 2] = lb * (float)Eexp;
    }
}

// =====================================================================
// ffn1_mma: act[m, n0..n0+63] = rtf(wt * silu(X@Wg^T) * (X@Wu^T))
// z = 0..7 routed (gathered, wt folded), z = 8 shared (dense).
// All fills cp.async.ca. B frags rounded post-LDSM. 2m x 4n warps.
// 2-stage, race-free (wait -> sync -> issue). 256 thr, 2 CTAs/SM.
// =====================================================================
#define STG1F 9216
#define STG1B (STG1F * 4)
__global__ __launch_bounds__(256, 2) void ffn1_mma(
    const float* __restrict__ Xr,
    const float* __restrict__ gw,
    const float* __restrict__ uw,
    const float* __restrict__ shg,
    const float* __restrict__ shu,
    float* __restrict__ actR,
    float* __restrict__ actS)
{
    int e = blockIdx.z;
    bool is_sh = (e == Eexp);
    int M = is_sh ? Ntok : g_count[e];
    int m0 = blockIdx.y * 128;
    if (m0 >= M) return;
    int n0 = blockIdx.x * 64;

    const float* Wg = is_sh ? shg : gw + (size_t)e * Hdim * Ddim;
    const float* Wu = is_sh ? shu : uw + (size_t)e * Hdim * Ddim;
    float* act = is_sh ? actS : actR + (size_t)e * Ntok * Hdim;
    const int* rowidx = is_sh ? nullptr : g_list + e * Ntok;
    const float* wl   = is_sh ? nullptr : g_wlist + e * Ntok;

    extern __shared__ float sm[];
    uint32_t smbase = smem_u32(sm);

    int tid = threadIdx.x, lane = tid & 31, wid = tid >> 5;
    int g = lane >> 2, tig = lane & 3;
    int wm = wid & 1, wn = wid >> 1;        // 2m x 4n
    int mw = wm * 64, nw = wn * 16;

    int lr = tid >> 3, lc = tid & 7;
    const float* aptr[4];
    #pragma unroll
    for (int i = 0; i < 4; i++) {
        int mm = m0 + lr + 32 * i;
        int src = mm < M ? mm : (M - 1);
        int row = rowidx ? rowidx[src] : src;
        aptr[i] = Xr + (size_t)row * Ddim + lc * 4;
    }
    const float *gptr[2], *uptr[2];
    #pragma unroll
    for (int i = 0; i < 2; i++) {
        int r = n0 + lr + 32 * i;
        gptr[i] = Wg + (size_t)r * Ddim + lc * 4;
        uptr[i] = Wu + (size_t)r * Ddim + lc * 4;
    }
    uint32_t dA[4], dG[2], dU[2];
    #pragma unroll
    for (int i = 0; i < 4; i++) dA[i] = ((lr + 32 * i) * 36 + lc * 4) * 4;
    #pragma unroll
    for (int i = 0; i < 2; i++) {
        dG[i] = (4608 + (lr + 32 * i) * 36 + lc * 4) * 4;
        dU[i] = dG[i] + 2304 * 4;
    }

    uint32_t afoff[4];
    #pragma unroll
    for (int mf = 0; mf < 4; mf++)
        afoff[mf] = ((mw + mf * 16 + (lane & 15)) * 36 + ((lane >> 4) << 2)) * 4;
    uint32_t bgoff, buoff;
    {
        int nrow = nw + ((lane >> 4) << 3) + (lane & 7);
        int cadd = ((lane >> 3) & 1) << 2;
        bgoff = (4608 + nrow * 36 + cadd) * 4;
        buoff = bgoff + 2304 * 4;
    }

    float accg[4][2][4], accu[4][2][4];
    #pragma unroll
    for (int a = 0; a < 4; a++)
        #pragma unroll
        for (int b = 0; b < 2; b++)
            #pragma unroll
            for (int c = 0; c < 4; c++) { accg[a][b][c] = 0.f; accu[a][b][c] = 0.f; }

    {
        uint32_t sb = smbase;
        #pragma unroll
        for (int i = 0; i < 4; i++) cpa16(sb + dA[i], aptr[i]);
        #pragma unroll
        for (int i = 0; i < 2; i++) { cpa16(sb + dG[i], gptr[i]); cpa16(sb + dU[i], uptr[i]); }
        CP_COMMIT();
    }

    const int NT = Ddim / 32;
    for (int kt = 0; kt < NT; kt++) {
        int cur = kt & 1;
        CP_WAIT0();
        __syncthreads();
        if (kt + 1 < NT) {
            uint32_t sb = smbase + (uint32_t)(cur ^ 1) * STG1B;
            int off = (kt + 1) * 32;
            #pragma unroll
            for (int i = 0; i < 4; i++) cpa16(sb + dA[i], aptr[i] + off);
            #pragma unroll
            for (int i = 0; i < 2; i++) { cpa16(sb + dG[i], gptr[i] + off); cpa16(sb + dU[i], uptr[i] + off); }
            CP_COMMIT();
        }
        uint32_t stb = smbase + (uint32_t)cur * STG1B;
        #pragma unroll
        for (int s = 0; s < 4; s++) {
            uint32_t koff = s * 32;
            uint32_t af[4][4], bg[4], bu[4];
            ldsm4(af[0], stb + afoff[0] + koff);
            ldsm4(af[1], stb + afoff[1] + koff);
            ldsm4(af[2], stb + afoff[2] + koff);
            ldsm4(af[3], stb + afoff[3] + koff);
            ldsm4(bg, stb + bgoff + koff);
            ldsm4(bu, stb + buoff + koff);
            #pragma unroll
            for (int j = 0; j < 4; j++) { bg[j] = rtfb(bg[j]); bu[j] = rtfb(bu[j]); }
            #pragma unroll
            for (int mf = 0; mf < 4; mf++) {
                mma_tf32(accg[mf][0], af[mf], bg[0], bg[1]);
                mma_tf32(accg[mf][1], af[mf], bg[2], bg[3]);
                mma_tf32(accu[mf][0], af[mf], bu[0], bu[1]);
                mma_tf32(accu[mf][1], af[mf], bu[2], bu[3]);
            }
        }
    }

    #pragma unroll
    for (int mf = 0; mf < 4; mf++) {
        int m1 = m0 + mw + mf * 16 + g;
        int m2 = m1 + 8;
        float wt1 = (m1 < M) ? (wl ? wl[m1] : 1.f) : 0.f;
        float wt2 = (m2 < M) ? (wl ? wl[m2] : 1.f) : 0.f;
        #pragma unroll
        for (int nf = 0; nf < 2; nf++) {
            int n = n0 + nw + nf * 8 + 2 * tig;
            if (m1 < M) {
                float2 o;
                o.x = rtf(wt1 * silu(accg[mf][nf][0]) * accu[mf][nf][0]);
                o.y = rtf(wt1 * silu(accg[mf][nf][1]) * accu[mf][nf][1]);
                *reinterpret_cast<float2*>(act + (size_t)m1 * Hdim + n) = o;
            }
            if (m2 < M) {
                float2 o;
                o.x = rtf(wt2 * silu(accg[mf][nf][2]) * accu[mf][nf][2]);
                o.y = rtf(wt2 * silu(accg[mf][nf][3]) * accu[mf][nf][3]);
                *reinterpret_cast<float2*>(act + (size_t)m2 * Hdim + n) = o;
            }
        }
    }
}

// =====================================================================
// ffn2_mma: out += ACT @ Wd^T  (all atomic; out pre-zeroed by router)
// z = 0..7 routed, z = 8 shared. All fills .ca. 2-stage, race-free.
// =====================================================================
#define STG2F 9216
#define STG2B (STG2F * 4)
__global__ __launch_bounds__(256, 2) void ffn2_mma(
    const float* __restrict__ actRb,
    const float* __restrict__ actSb,
    const float* __restrict__ dw,
    const float* __restrict__ shd,
    float* __restrict__ OUT)
{
    int e = blockIdx.z;
    bool is_sh = (e == Eexp);
    int M = is_sh ? Ntok : g_count[e];
    int m0 = blockIdx.y * 128;
    if (m0 >= M) return;
    int n0 = blockIdx.x * 128;

    const float* Wd  = is_sh ? shd : dw + (size_t)e * Ddim * Hdim;
    const float* act = is_sh ? actSb : actRb + (size_t)e * Ntok * Hdim;
    const int* rowidx = is_sh ? nullptr : g_list + e * Ntok;

    extern __shared__ float sm[];
    uint32_t smbase = smem_u32(sm);

    int tid = threadIdx.x, lane = tid & 31, wid = tid >> 5;
    int g = lane >> 2, tig = lane & 3;
    int wm = wid >> 2, wn = wid & 3;
    int mw = wm * 64, nw = wn * 32;

    int lr = tid >> 3, lc = tid & 7;
    const float* aptr[4];
    const float* bptr[4];
    #pragma unroll
    for (int i = 0; i < 4; i++) {
        int mm = m0 + lr + 32 * i;
        int src = mm < M ? mm : (M - 1);
        aptr[i] = act + (size_t)src * Hdim + lc * 4;
        bptr[i] = Wd  + (size_t)(n0 + lr + 32 * i) * Hdim + lc * 4;
    }
    uint32_t dA[4], dB[4];
    #pragma unroll
    for (int i = 0; i < 4; i++) {
        dA[i] = ((lr + 32 * i) * 36 + lc * 4) * 4;
        dB[i] = (4608 + (lr + 32 * i) * 36 + lc * 4) * 4;
    }

    uint32_t afoff[4];
    #pragma unroll
    for (int mf = 0; mf < 4; mf++)
        afoff[mf] = ((mw + mf * 16 + (lane & 15)) * 36 + ((lane >> 4) << 2)) * 4;
    uint32_t bfoff[2];
    {
        int nrow = nw + ((lane >> 4) << 3) + (lane & 7);
        int cadd = ((lane >> 3) & 1) << 2;
        #pragma unroll
        for (int p = 0; p < 2; p++)
            bfoff[p] = (4608 + (nrow + p * 16) * 36 + cadd) * 4;
    }

    float acc[4][4][4];
    #pragma unroll
    for (int a = 0; a < 4; a++)
        #pragma unroll
        for (int b = 0; b < 4; b++)
            #pragma unroll
            for (int c = 0; c < 4; c++) acc[a][b][c] = 0.f;

    {
        uint32_t sb = smbase;
        #pragma unroll
        for (int i = 0; i < 4; i++) { cpa16(sb + dA[i], aptr[i]); cpa16(sb + dB[i], bptr[i]); }
        CP_COMMIT();
    }

    const int NT = Hdim / 32;
    for (int kt = 0; kt < NT; kt++) {
        int cur = kt & 1;
        CP_WAIT0();
        __syncthreads();
        if (kt + 1 < NT) {
            uint32_t sb = smbase + (uint32_t)(cur ^ 1) * STG2B;
            int off = (kt + 1) * 32;
            #pragma unroll
            for (int i = 0; i < 4; i++) { cpa16(sb + dA[i], aptr[i] + off); cpa16(sb + dB[i], bptr[i] + off); }
            CP_COMMIT();
        }
        uint32_t stb = smbase + (uint32_t)cur * STG2B;
        #pragma unroll
        for (int s = 0; s < 4; s++) {
            uint32_t koff = s * 32;
            uint32_t af[4][4], bf[2][4];
            ldsm4(af[0], stb + afoff[0] + koff);
            ldsm4(af[1], stb + afoff[1] + koff);
            ldsm4(af[2], stb + afoff[2] + koff);
            ldsm4(af[3], stb + afoff[3] + koff);
            ldsm4(bf[0], stb + bfoff[0] + koff);
            ldsm4(bf[1], stb + bfoff[1] + koff);
            #pragma unroll
            for (int p = 0; p < 2; p++)
                #pragma unroll
                for (int j = 0; j < 4; j++) bf[p][j] = rtfb(bf[p][j]);
            #pragma unroll
            for (int mf = 0; mf < 4; mf++)
                #pragma unroll
                for (int p = 0; p < 2; p++) {
                    mma_tf32(acc[mf][2*p  ], af[mf], bf[p][0], bf[p][1]);
                    mma_tf32(acc[mf][2*p+1], af[mf], bf[p][2], bf[p][3]);
                }
        }
    }

    #pragma unroll
    for (int mf = 0; mf < 4; mf++) {
        int m1 = m0 + mw + mf * 16 + g;
        int m2 = m1 + 8;
        #pragma unroll
        for (int nf = 0; nf < 4; nf++) {
            int n = n0 + nw + nf * 8 + 2 * tig;
            if (m1 < M) {
                int tok = rowidx ? rowidx[m1] : m1;
                float* p = OUT + (size_t)tok * Ddim + n;
                atomicAdd(p,     acc[mf][nf][0]);
                atomicAdd(p + 1, acc[mf][nf][1]);
            }
            if (m2 < M) {
                int tok = rowidx ? rowidx[m2] : m2;
                float* p = OUT + (size_t)tok * Ddim + n;
                atomicAdd(p,     acc[mf][nf][2]);
                atomicAdd(p + 1, acc[mf][nf][3]);
            }
        }
    }
}

// ---------------- launch ----------------
#define FFN1_SMEM (2 * STG1B)
#define FFN2_SMEM (2 * STG2B)

extern "C" void kernel_launch(void* const* d_in, const int* in_sizes, int n_in,
                              void* d_out, int out_size)
{
    const float* x   = (const float*)d_in[0];
    const float* rw  = (const float*)d_in[1];
    const float* rb  = (const float*)d_in[2];
    const float* gw  = (const float*)d_in[3];
    const float* uw  = (const float*)d_in[4];
    const float* dw  = (const float*)d_in[5];
    const float* shg = (const float*)d_in[6];
    const float* shu = (const float*)d_in[7];
    const float* shd = (const float*)d_in[8];
    float* out = (float*)d_out;

    float *act_r, *act_s, *x_r;
    cudaGetSymbolAddress((void**)&act_r, g_act_r);
    cudaGetSymbolAddress((void**)&act_s, g_act_s);
    cudaGetSymbolAddress((void**)&x_r,   g_x_r);

    cudaFuncSetAttribute(ffn1_mma, cudaFuncAttributeMaxDynamicSharedMemorySize, FFN1_SMEM);
    cudaFuncSetAttribute(ffn2_mma, cudaFuncAttributeMaxDynamicSharedMemorySize, FFN2_SMEM);

    init_kernel<<<1, 32>>>();
    // router: logits/top-2/lists + tf32 x + zeroes out (fold removes one launch)
    router_kernel<<<Ntok / 8, 256>>>(x, rw, rb, x_r, (float4*)out);
    finalize_kernel<<<1, 1>>>(out, out_size);

    // gate/up + SwiGLU: z 0..7 routed (wt folded), z 8 shared — single launch
    ffn1_mma<<<dim3(Hdim/64, Ntok/128, Eexp + 1), 256, FFN1_SMEM>>>(
        x_r, gw, uw, shg, shu, act_r, act_s);

    // down-proj: single all-atomic launch over pre-zeroed out
    ffn2_mma<<<dim3(Ddim/128, Ntok/128, Eexp + 1), 256, FFN2_SMEM>>>(
        act_r, act_s, dw, shd, out);
}

// round 17
// speedup vs baseline: 1.0563x; 1.0049x over previous
#include <cuda_runtime.h>
#include <cstdint>

// Problem constants (B=2, S=1024, D=1024, E=8, K=2, H=2048)
#define Ntok 2048
#define Ddim 1024
#define Eexp 8
#define Hdim 2048
#define BSD  (2*1024*1024)
#define ZCOEF 1e-4f

// ---------------- scratch (static device globals) ----------------
__device__ float g_zsum;
__device__ float g_psum[Eexp];
__device__ int   g_count[Eexp];
__device__ int   g_list[Eexp * Ntok];
__device__ float g_wlist[Eexp * Ntok];
__device__ float g_act_r[(size_t)Eexp * Ntok * Hdim];   // routed SwiGLU act (wt folded, tf32-rounded)
__device__ float g_act_s[(size_t)Ntok * Hdim];          // shared-expert act (tf32-rounded)
__device__ float g_x_r[(size_t)Ntok * Ddim];            // tf32-rounded x (written by router)

// ---------------- helpers ----------------
__device__ __forceinline__ float rtf(float x) {
    uint32_t r;
    asm("cvt.rna.tf32.f32 %0, %1;" : "=r"(r) : "f"(x));
    return __uint_as_float(r);
}
__device__ __forceinline__ uint32_t rtfb(uint32_t x) {
    uint32_t r;
    asm("cvt.rna.tf32.f32 %0, %1;" : "=r"(r) : "f"(__uint_as_float(x)));
    return r;
}
__device__ __forceinline__ void mma_tf32(float c[4],
    const uint32_t a[4], uint32_t b0, uint32_t b1)
{
    asm volatile(
        "mma.sync.aligned.m16n8k8.row.col.f32.tf32.tf32.f32 "
        "{%0,%1,%2,%3}, {%4,%5,%6,%7}, {%8,%9}, {%0,%1,%2,%3};"
        : "+f"(c[0]), "+f"(c[1]), "+f"(c[2]), "+f"(c[3])
        : "r"(a[0]), "r"(a[1]), "r"(a[2]), "r"(a[3]), "r"(b0), "r"(b1));
}
__device__ __forceinline__ void ldsm4(uint32_t r[4], uint32_t addr) {
    asm volatile("ldmatrix.sync.aligned.m8n8.x4.shared.b16 {%0,%1,%2,%3}, [%4];"
        : "=r"(r[0]), "=r"(r[1]), "=r"(r[2]), "=r"(r[3]) : "r"(addr));
}
__device__ __forceinline__ uint32_t smem_u32(const void* p) {
    uint32_t a;
    asm("{ .reg .u64 t; cvta.to.shared.u64 t, %1; cvt.u32.u64 %0, t; }" : "=r"(a) : "l"(p));
    return a;
}
__device__ __forceinline__ void cpa16(uint32_t dst, const float* src) {
    asm volatile("cp.async.ca.shared.global [%0], [%1], 16;" :: "r"(dst), "l"(src));
}
#define CP_COMMIT() asm volatile("cp.async.commit_group;" ::: "memory")
#define CP_WAIT0()  asm volatile("cp.async.wait_group 0;" ::: "memory")
__device__ __forceinline__ float silu(float x) { return x / (1.f + __expf(-x)); }

// ---------------- init ----------------
__global__ void init_kernel() {
    int t = threadIdx.x;
    if (t == 0) g_zsum = 0.f;
    if (t < Eexp) { g_psum[t] = 0.f; g_count[t] = 0; }
}

// ---------------- router: 8 tokens/block; emits tf32 x; zeroes out ----------------
__global__ __launch_bounds__(256) void router_kernel(
    const float* __restrict__ x,
    const float* __restrict__ rw,
    const float* __restrict__ rb,
    float* __restrict__ xr_out,
    float4* __restrict__ out_zero)
{
    __shared__ float srw[Eexp * Ddim];   // 32 KB
    int tid = threadIdx.x;
    {
        const float4* rw4 = reinterpret_cast<const float4*>(rw);
        float4* srw4 = reinterpret_cast<float4*>(srw);
        #pragma unroll
        for (int i = 0; i < (Eexp * Ddim / 4) / 256; i++)
            srw4[tid + i * 256] = rw4[tid + i * 256];
    }

    // zero the output (256 blocks x 256 threads x 8 float4 == BSD floats)
    {
        int base = blockIdx.x * 256 * 8 + tid;
        #pragma unroll
        for (int i = 0; i < 8; i++)
            out_zero[base + i * 256] = make_float4(0.f, 0.f, 0.f, 0.f);
    }
    __syncthreads();

    int wid = tid >> 5, lane = tid & 31;
    int n = blockIdx.x * 8 + wid;

    const float4* xr = reinterpret_cast<const float4*>(x + (size_t)n * Ddim);
    float4 xv[8];
    #pragma unroll
    for (int i = 0; i < 8; i++) xv[i] = xr[lane + i * 32];

    // write tf32-rounded x
    {
        float4* xo = reinterpret_cast<float4*>(xr_out + (size_t)n * Ddim);
        #pragma unroll
        for (int i = 0; i < 8; i++) {
            float4 t;
            t.x = rtf(xv[i].x); t.y = rtf(xv[i].y); t.z = rtf(xv[i].z); t.w = rtf(xv[i].w);
            xo[lane + i * 32] = t;
        }
    }

    float myLogit = 0.f;
    #pragma unroll
    for (int e = 0; e < Eexp; e++) {
        const float4* we = reinterpret_cast<const float4*>(srw + e * Ddim);
        float s = 0.f;
        #pragma unroll
        for (int i = 0; i < 8; i++) {
            float4 wv = we[lane + i * 32];
            s += xv[i].x * wv.x + xv[i].y * wv.y + xv[i].z * wv.z + xv[i].w * wv.w;
        }
        #pragma unroll
        for (int o = 16; o; o >>= 1) s += __shfl_xor_sync(0xFFFFFFFFu, s, o);
        if (lane == e) myLogit = s;
    }
    float l[Eexp];
    #pragma unroll
    for (int e = 0; e < Eexp; e++) l[e] = __shfl_sync(0xFFFFFFFFu, myLogit, e);

    if (lane == 0) {
        float bsd[Eexp];
        float mx = -1e30f;
        #pragma unroll
        for (int e = 0; e < Eexp; e++) {
            bsd[e] = l[e] + rb[e];
            mx = fmaxf(mx, l[e]);
        }
        int i0 = 0;
        #pragma unroll
        for (int e = 1; e < Eexp; e++) if (bsd[e] > bsd[i0]) i0 = e;
        int i1 = (i0 == 0) ? 1 : 0;
        #pragma unroll
        for (int e = 0; e < Eexp; e++) if (e != i0 && bsd[e] > bsd[i1]) i1 = e;

        float l0 = l[i0], l1 = l[i1];
        float m2 = fmaxf(l0, l1);
        float e0 = expf(l0 - m2), e1 = expf(l1 - m2);
        float inv = 1.f / (e0 + e1);
        float w0 = e0 * inv, w1 = e1 * inv;

        float se = 0.f;
        #pragma unroll
        for (int e = 0; e < Eexp; e++) se += expf(l[e] - mx);
        float z = mx + logf(se);
        atomicAdd(&g_zsum, z * z);
        #pragma unroll
        for (int e = 0; e < Eexp; e++) atomicAdd(&g_psum[e], expf(l[e] - z));

        int p0 = atomicAdd(&g_count[i0], 1);
        g_list[i0 * Ntok + p0]  = n;
        g_wlist[i0 * Ntok + p0] = w0;
        int p1 = atomicAdd(&g_count[i1], 1);
        g_list[i1 * Ntok + p1]  = n;
        g_wlist[i1 * Ntok + p1] = w1;
    }
}

// =====================================================================
// ffn1_mma: act[m, n0..n0+63] = rtf(wt * silu(X@Wg^T) * (X@Wu^T))
// z = 0..7 routed (gathered, wt folded), z = 8 shared (dense).
// Block (0,0,8) thread 0 also emits the three scalar outputs
// (router completed before this kernel by stream order).
// All fills cp.async.ca. B frags rounded post-LDSM. 2m x 4n warps.
// 2-stage, race-free (wait -> sync -> issue). 256 thr, 2 CTAs/SM.
// =====================================================================
#define STG1F 9216
#define STG1B (STG1F * 4)
__global__ __launch_bounds__(256, 2) void ffn1_mma(
    const float* __restrict__ Xr,
    const float* __restrict__ gw,
    const float* __restrict__ uw,
    const float* __restrict__ shg,
    const float* __restrict__ shu,
    float* __restrict__ actR,
    float* __restrict__ actS,
    float* __restrict__ out, int out_size)
{
    int e = blockIdx.z;
    bool is_sh = (e == Eexp);

    // folded finalize: scalar outputs (aux, z-loss, load-balance)
    if (is_sh && blockIdx.x == 0 && blockIdx.y == 0 && threadIdx.x == 0 &&
        out_size >= BSD + 3) {
        float lb = 0.f;
        #pragma unroll
        for (int k = 0; k < Eexp; k++)
            lb += (g_psum[k] / (float)Ntok) * ((float)g_count[k] / (float)Ntok);
        out[BSD + 0] = 0.f;
        out[BSD + 1] = g_zsum / (float)Ntok * ZCOEF;
        out[BSD + 2] = lb * (float)Eexp;
    }

    int M = is_sh ? Ntok : g_count[e];
    int m0 = blockIdx.y * 128;
    if (m0 >= M) return;
    int n0 = blockIdx.x * 64;

    const float* Wg = is_sh ? shg : gw + (size_t)e * Hdim * Ddim;
    const float* Wu = is_sh ? shu : uw + (size_t)e * Hdim * Ddim;
    float* act = is_sh ? actS : actR + (size_t)e * Ntok * Hdim;
    const int* rowidx = is_sh ? nullptr : g_list + e * Ntok;
    const float* wl   = is_sh ? nullptr : g_wlist + e * Ntok;

    extern __shared__ float sm[];
    uint32_t smbase = smem_u32(sm);

    int tid = threadIdx.x, lane = tid & 31, wid = tid >> 5;
    int g = lane >> 2, tig = lane & 3;
    int wm = wid & 1, wn = wid >> 1;        // 2m x 4n
    int mw = wm * 64, nw = wn * 16;

    int lr = tid >> 3, lc = tid & 7;
    const float* aptr[4];
    #pragma unroll
    for (int i = 0; i < 4; i++) {
        int mm = m0 + lr + 32 * i;
        int src = mm < M ? mm : (M - 1);
        int row = rowidx ? rowidx[src] : src;
        aptr[i] = Xr + (size_t)row * Ddim + lc * 4;
    }
    const float *gptr[2], *uptr[2];
    #pragma unroll
    for (int i = 0; i < 2; i++) {
        int r = n0 + lr + 32 * i;
        gptr[i] = Wg + (size_t)r * Ddim + lc * 4;
        uptr[i] = Wu + (size_t)r * Ddim + lc * 4;
    }
    uint32_t dA[4], dG[2], dU[2];
    #pragma unroll
    for (int i = 0; i < 4; i++) dA[i] = ((lr + 32 * i) * 36 + lc * 4) * 4;
    #pragma unroll
    for (int i = 0; i < 2; i++) {
        dG[i] = (4608 + (lr + 32 * i) * 36 + lc * 4) * 4;
        dU[i] = dG[i] + 2304 * 4;
    }

    uint32_t afoff[4];
    #pragma unroll
    for (int mf = 0; mf < 4; mf++)
        afoff[mf] = ((mw + mf * 16 + (lane & 15)) * 36 + ((lane >> 4) << 2)) * 4;
    uint32_t bgoff, buoff;
    {
        int nrow = nw + ((lane >> 4) << 3) + (lane & 7);
        int cadd = ((lane >> 3) & 1) << 2;
        bgoff = (4608 + nrow * 36 + cadd) * 4;
        buoff = bgoff + 2304 * 4;
    }

    float accg[4][2][4], accu[4][2][4];
    #pragma unroll
    for (int a = 0; a < 4; a++)
        #pragma unroll
        for (int b = 0; b < 2; b++)
            #pragma unroll
            for (int c = 0; c < 4; c++) { accg[a][b][c] = 0.f; accu[a][b][c] = 0.f; }

    {
        uint32_t sb = smbase;
        #pragma unroll
        for (int i = 0; i < 4; i++) cpa16(sb + dA[i], aptr[i]);
        #pragma unroll
        for (int i = 0; i < 2; i++) { cpa16(sb + dG[i], gptr[i]); cpa16(sb + dU[i], uptr[i]); }
        CP_COMMIT();
    }

    const int NT = Ddim / 32;
    for (int kt = 0; kt < NT; kt++) {
        int cur = kt & 1;
        CP_WAIT0();
        __syncthreads();
        if (kt + 1 < NT) {
            uint32_t sb = smbase + (uint32_t)(cur ^ 1) * STG1B;
            int off = (kt + 1) * 32;
            #pragma unroll
            for (int i = 0; i < 4; i++) cpa16(sb + dA[i], aptr[i] + off);
            #pragma unroll
            for (int i = 0; i < 2; i++) { cpa16(sb + dG[i], gptr[i] + off); cpa16(sb + dU[i], uptr[i] + off); }
            CP_COMMIT();
        }
        uint32_t stb = smbase + (uint32_t)cur * STG1B;
        #pragma unroll
        for (int s = 0; s < 4; s++) {
            uint32_t koff = s * 32;
            uint32_t af[4][4], bg[4], bu[4];
            ldsm4(af[0], stb + afoff[0] + koff);
            ldsm4(af[1], stb + afoff[1] + koff);
            ldsm4(af[2], stb + afoff[2] + koff);
            ldsm4(af[3], stb + afoff[3] + koff);
            ldsm4(bg, stb + bgoff + koff);
            ldsm4(bu, stb + buoff + koff);
            #pragma unroll
            for (int j = 0; j < 4; j++) { bg[j] = rtfb(bg[j]); bu[j] = rtfb(bu[j]); }
            #pragma unroll
            for (int mf = 0; mf < 4; mf++) {
                mma_tf32(accg[mf][0], af[mf], bg[0], bg[1]);
                mma_tf32(accg[mf][1], af[mf], bg[2], bg[3]);
                mma_tf32(accu[mf][0], af[mf], bu[0], bu[1]);
                mma_tf32(accu[mf][1], af[mf], bu[2], bu[3]);
            }
        }
    }

    #pragma unroll
    for (int mf = 0; mf < 4; mf++) {
        int m1 = m0 + mw + mf * 16 + g;
        int m2 = m1 + 8;
        float wt1 = (m1 < M) ? (wl ? wl[m1] : 1.f) : 0.f;
        float wt2 = (m2 < M) ? (wl ? wl[m2] : 1.f) : 0.f;
        #pragma unroll
        for (int nf = 0; nf < 2; nf++) {
            int n = n0 + nw + nf * 8 + 2 * tig;
            if (m1 < M) {
                float2 o;
                o.x = rtf(wt1 * silu(accg[mf][nf][0]) * accu[mf][nf][0]);
                o.y = rtf(wt1 * silu(accg[mf][nf][1]) * accu[mf][nf][1]);
                *reinterpret_cast<float2*>(act + (size_t)m1 * Hdim + n) = o;
            }
            if (m2 < M) {
                float2 o;
                o.x = rtf(wt2 * silu(accg[mf][nf][2]) * accu[mf][nf][2]);
                o.y = rtf(wt2 * silu(accg[mf][nf][3]) * accu[mf][nf][3]);
                *reinterpret_cast<float2*>(act + (size_t)m2 * Hdim + n) = o;
            }
        }
    }
}

// =====================================================================
// ffn2_mma: out += ACT @ Wd^T  (all atomic; out pre-zeroed by router)
// z = 0..7 routed, z = 8 shared. All fills .ca. 2-stage, race-free.
// =====================================================================
#define STG2F 9216
#define STG2B (STG2F * 4)
__global__ __launch_bounds__(256, 2) void ffn2_mma(
    const float* __restrict__ actRb,
    const float* __restrict__ actSb,
    const float* __restrict__ dw,
    const float* __restrict__ shd,
    float* __restrict__ OUT)
{
    int e = blockIdx.z;
    bool is_sh = (e == Eexp);
    int M = is_sh ? Ntok : g_count[e];
    int m0 = blockIdx.y * 128;
    if (m0 >= M) return;
    int n0 = blockIdx.x * 128;

    const float* Wd  = is_sh ? shd : dw + (size_t)e * Ddim * Hdim;
    const float* act = is_sh ? actSb : actRb + (size_t)e * Ntok * Hdim;
    const int* rowidx = is_sh ? nullptr : g_list + e * Ntok;

    extern __shared__ float sm[];
    uint32_t smbase = smem_u32(sm);

    int tid = threadIdx.x, lane = tid & 31, wid = tid >> 5;
    int g = lane >> 2, tig = lane & 3;
    int wm = wid >> 2, wn = wid & 3;
    int mw = wm * 64, nw = wn * 32;

    int lr = tid >> 3, lc = tid & 7;
    const float* aptr[4];
    const float* bptr[4];
    #pragma unroll
    for (int i = 0; i < 4; i++) {
        int mm = m0 + lr + 32 * i;
        int src = mm < M ? mm : (M - 1);
        aptr[i] = act + (size_t)src * Hdim + lc * 4;
        bptr[i] = Wd  + (size_t)(n0 + lr + 32 * i) * Hdim + lc * 4;
    }
    uint32_t dA[4], dB[4];
    #pragma unroll
    for (int i = 0; i < 4; i++) {
        dA[i] = ((lr + 32 * i) * 36 + lc * 4) * 4;
        dB[i] = (4608 + (lr + 32 * i) * 36 + lc * 4) * 4;
    }

    uint32_t afoff[4];
    #pragma unroll
    for (int mf = 0; mf < 4; mf++)
        afoff[mf] = ((mw + mf * 16 + (lane & 15)) * 36 + ((lane >> 4) << 2)) * 4;
    uint32_t bfoff[2];
    {
        int nrow = nw + ((lane >> 4) << 3) + (lane & 7);
        int cadd = ((lane >> 3) & 1) << 2;
        #pragma unroll
        for (int p = 0; p < 2; p++)
            bfoff[p] = (4608 + (nrow + p * 16) * 36 + cadd) * 4;
    }

    float acc[4][4][4];
    #pragma unroll
    for (int a = 0; a < 4; a++)
        #pragma unroll
        for (int b = 0; b < 4; b++)
            #pragma unroll
            for (int c = 0; c < 4; c++) acc[a][b][c] = 0.f;

    {
        uint32_t sb = smbase;
        #pragma unroll
        for (int i = 0; i < 4; i++) { cpa16(sb + dA[i], aptr[i]); cpa16(sb + dB[i], bptr[i]); }
        CP_COMMIT();
    }

    const int NT = Hdim / 32;
    for (int kt = 0; kt < NT; kt++) {
        int cur = kt & 1;
        CP_WAIT0();
        __syncthreads();
        if (kt + 1 < NT) {
            uint32_t sb = smbase + (uint32_t)(cur ^ 1) * STG2B;
            int off = (kt + 1) * 32;
            #pragma unroll
            for (int i = 0; i < 4; i++) { cpa16(sb + dA[i], aptr[i] + off); cpa16(sb + dB[i], bptr[i] + off); }
            CP_COMMIT();
        }
        uint32_t stb = smbase + (uint32_t)cur * STG2B;
        #pragma unroll
        for (int s = 0; s < 4; s++) {
            uint32_t koff = s * 32;
            uint32_t af[4][4], bf[2][4];
            ldsm4(af[0], stb + afoff[0] + koff);
            ldsm4(af[1], stb + afoff[1] + koff);
            ldsm4(af[2], stb + afoff[2] + koff);
            ldsm4(af[3], stb + afoff[3] + koff);
            ldsm4(bf[0], stb + bfoff[0] + koff);
            ldsm4(bf[1], stb + bfoff[1] + koff);
            #pragma unroll
            for (int p = 0; p < 2; p++)
                #pragma unroll
                for (int j = 0; j < 4; j++) bf[p][j] = rtfb(bf[p][j]);
            #pragma unroll
            for (int mf = 0; mf < 4; mf++)
                #pragma unroll
                for (int p = 0; p < 2; p++) {
                    mma_tf32(acc[mf][2*p  ], af[mf], bf[p][0], bf[p][1]);
                    mma_tf32(acc[mf][2*p+1], af[mf], bf[p][2], bf[p][3]);
                }
        }
    }

    #pragma unroll
    for (int mf = 0; mf < 4; mf++) {
        int m1 = m0 + mw + mf * 16 + g;
        int m2 = m1 + 8;
        #pragma unroll
        for (int nf = 0; nf < 4; nf++) {
            int n = n0 + nw + nf * 8 + 2 * tig;
            if (m1 < M) {
                int tok = rowidx ? rowidx[m1] : m1;
                float* p = OUT + (size_t)tok * Ddim + n;
                atomicAdd(p,     acc[mf][nf][0]);
                atomicAdd(p + 1, acc[mf][nf][1]);
            }
            if (m2 < M) {
                int tok = rowidx ? rowidx[m2] : m2;
                float* p = OUT + (size_t)tok * Ddim + n;
                atomicAdd(p,     acc[mf][nf][2]);
                atomicAdd(p + 1, acc[mf][nf][3]);
            }
        }
    }
}

// ---------------- launch ----------------
#define FFN1_SMEM (2 * STG1B)
#define FFN2_SMEM (2 * STG2B)

extern "C" void kernel_launch(void* const* d_in, const int* in_sizes, int n_in,
                              void* d_out, int out_size)
{
    const float* x   = (const float*)d_in[0];
    const float* rw  = (const float*)d_in[1];
    const float* rb  = (const float*)d_in[2];
    const float* gw  = (const float*)d_in[3];
    const float* uw  = (const float*)d_in[4];
    const float* dw  = (const float*)d_in[5];
    const float* shg = (const float*)d_in[6];
    const float* shu = (const float*)d_in[7];
    const float* shd = (const float*)d_in[8];
    float* out = (float*)d_out;

    float *act_r, *act_s, *x_r;
    cudaGetSymbolAddress((void**)&act_r, g_act_r);
    cudaGetSymbolAddress((void**)&act_s, g_act_s);
    cudaGetSymbolAddress((void**)&x_r,   g_x_r);

    cudaFuncSetAttribute(ffn1_mma, cudaFuncAttributeMaxDynamicSharedMemorySize, FFN1_SMEM);
    cudaFuncSetAttribute(ffn2_mma, cudaFuncAttributeMaxDynamicSharedMemorySize, FFN2_SMEM);

    init_kernel<<<1, 32>>>();
    // router: logits/top-2/lists + tf32 x + zeroes out
    router_kernel<<<Ntok / 8, 256>>>(x, rw, rb, x_r, (float4*)out);

    // gate/up + SwiGLU: z 0..7 routed (wt folded), z 8 shared — single launch;
    // block (0,0,8) also emits the three scalar outputs (finalize folded)
    ffn1_mma<<<dim3(Hdim/64, Ntok/128, Eexp + 1), 256, FFN1_SMEM>>>(
        x_r, gw, uw, shg, shu, act_r, act_s, out, out_size);

    // down-proj: single all-atomic launch over pre-zeroed out
    ffn2_mma<<<dim3(Ddim/128, Ntok/128, Eexp + 1), 256, FFN2_SMEM>>>(
        act_r, act_s, dw, shd, out);
}